// round 5
// baseline (speedup 1.0000x reference)
#include <cuda_runtime.h>
#include <math.h>

// Problem constants
#define PB   8
#define PS   2048
#define PD   512
#define PM   (PB * PS)          // 16384 rows flattened
#define SQD  0.044194173824159216f   // 1/sqrt(512)

// ---------------- scratch (no allocations allowed) ----------------
__device__ float g_q    [PB * PS * PD];   // 33.5 MB
__device__ float g_k    [PB * PS * PD];
__device__ float g_v    [PB * PS * PD];
__device__ float g_att  [PB * PS * PD];
__device__ float g_onxt [PB * PS * PD];
__device__ float g_sc   [PB * PS * PS];   // 134 MB; recycled for t1/h1/t2/h2

// ---------------- GEMM: C[M,N] = A[M,K] @ B + epilogue ----------------
// BT=false: B is [K,N] row-major (NN).  BT=true: B is [N,K] row-major (NT).
// EPI 0: C = acc (+ bias[n] if bias)            (QKV, att, final)
// EPI 1: C = acc * scale                        (scores)
// EPI 2: C = gelu(acc + bias[n] + res[m,n])     (FFN pre-LN)
#define BM 128
#define BN 128
#define BK 16

__device__ __forceinline__ float gelu_exact(float x) {
    return 0.5f * x * (1.0f + erff(x * 0.70710678118654752f));
}

template<int EPI, bool BT>
__global__ __launch_bounds__(256)
void gemm_kernel(const float* __restrict__ A, const float* __restrict__ B,
                 const float* __restrict__ bias, const float* __restrict__ res,
                 float* __restrict__ C, int M, int N, int K,
                 long long sA, long long sB, long long sC, float scale)
{
    __shared__ float As[BK][BM];
    __shared__ float Bs[BK][BN];

    const int tid = threadIdx.x;
    const int tx  = tid & 15;        // 0..15  -> 8 cols each
    const int ty  = tid >> 4;        // 0..15  -> 8 rows each
    const int m0  = blockIdx.y * BM;
    const int n0  = blockIdx.x * BN;

    A += (long long)blockIdx.z * sA;
    B += (long long)blockIdx.z * sB;
    C += (long long)blockIdx.z * sC;

    const int lda = K;
    const int ldb = BT ? K : N;

    float acc[8][8];
    #pragma unroll
    for (int i = 0; i < 8; i++)
        #pragma unroll
        for (int j = 0; j < 8; j++) acc[i][j] = 0.0f;

    for (int k0 = 0; k0 < K; k0 += BK) {
        // A tile [BM x BK] -> transposed store As[k][m]
        #pragma unroll
        for (int it = 0; it < 2; it++) {
            int f  = tid + it * 256;          // 0..511
            int r  = f >> 2;                  // 0..127
            int c4 = (f & 3) << 2;            // 0,4,8,12
            float4 va = *(const float4*)(A + (size_t)(m0 + r) * lda + k0 + c4);
            As[c4 + 0][r] = va.x; As[c4 + 1][r] = va.y;
            As[c4 + 2][r] = va.z; As[c4 + 3][r] = va.w;
        }
        if (BT) {
            // B tile [BN x BK] -> transposed store Bs[k][n]
            #pragma unroll
            for (int it = 0; it < 2; it++) {
                int f  = tid + it * 256;
                int r  = f >> 2;
                int c4 = (f & 3) << 2;
                float4 vb = *(const float4*)(B + (size_t)(n0 + r) * ldb + k0 + c4);
                Bs[c4 + 0][r] = vb.x; Bs[c4 + 1][r] = vb.y;
                Bs[c4 + 2][r] = vb.z; Bs[c4 + 3][r] = vb.w;
            }
        } else {
            // B tile [BK x BN] -> direct vector store
            #pragma unroll
            for (int it = 0; it < 2; it++) {
                int f  = tid + it * 256;
                int r  = f >> 5;                 // 0..15
                int c4 = (f & 31) << 2;          // 0..124
                float4 vb = *(const float4*)(B + (size_t)(k0 + r) * ldb + n0 + c4);
                *(float4*)&Bs[r][c4] = vb;
            }
        }
        __syncthreads();

        #pragma unroll
        for (int kk = 0; kk < BK; kk++) {
            float af[8], bf[8];
            #pragma unroll
            for (int i = 0; i < 8; i++) af[i] = As[kk][ty * 8 + i];
            #pragma unroll
            for (int j = 0; j < 8; j++) bf[j] = Bs[kk][tx * 8 + j];
            #pragma unroll
            for (int i = 0; i < 8; i++)
                #pragma unroll
                for (int j = 0; j < 8; j++)
                    acc[i][j] = fmaf(af[i], bf[j], acc[i][j]);
        }
        __syncthreads();
    }

    // epilogue (vectorized stores)
    #pragma unroll
    for (int i = 0; i < 8; i++) {
        size_t m = (size_t)(m0 + ty * 8 + i);
        #pragma unroll
        for (int j4 = 0; j4 < 2; j4++) {
            int n = n0 + tx * 8 + j4 * 4;
            float4 o;
            o.x = acc[i][j4 * 4 + 0]; o.y = acc[i][j4 * 4 + 1];
            o.z = acc[i][j4 * 4 + 2]; o.w = acc[i][j4 * 4 + 3];
            if (EPI == 1) {
                o.x *= scale; o.y *= scale; o.z *= scale; o.w *= scale;
            } else if (EPI == 0) {
                if (bias) {
                    float4 bb = *(const float4*)&bias[n];
                    o.x += bb.x; o.y += bb.y; o.z += bb.z; o.w += bb.w;
                }
            } else if (EPI == 2) {
                float4 bb = *(const float4*)&bias[n];
                float4 rr = *(const float4*)&res[m * (size_t)N + n];
                o.x = gelu_exact(o.x + bb.x + rr.x);
                o.y = gelu_exact(o.y + bb.y + rr.y);
                o.z = gelu_exact(o.z + bb.z + rr.z);
                o.w = gelu_exact(o.w + bb.w + rr.w);
            }
            *(float4*)&C[m * (size_t)N + n] = o;
        }
    }
}

// ---------------- row softmax over 2048 cols ----------------
__global__ __launch_bounds__(256)
void softmax_kernel(float* __restrict__ Sc)
{
    float* row = Sc + (size_t)blockIdx.x * PS;
    const int tid  = threadIdx.x;
    const int lane = tid & 31;
    const int wid  = tid >> 5;

    float v[8];
    float mx = -3.4e38f;
    #pragma unroll
    for (int i = 0; i < 8; i++) { v[i] = row[i * 256 + tid]; mx = fmaxf(mx, v[i]); }
    #pragma unroll
    for (int o = 16; o; o >>= 1) mx = fmaxf(mx, __shfl_xor_sync(0xffffffffu, mx, o));

    __shared__ float sm[8], ss[8];
    if (!lane) sm[wid] = mx;
    __syncthreads();
    mx = sm[0];
    #pragma unroll
    for (int i = 1; i < 8; i++) mx = fmaxf(mx, sm[i]);

    float s = 0.0f;
    #pragma unroll
    for (int i = 0; i < 8; i++) { v[i] = expf(v[i] - mx); s += v[i]; }
    #pragma unroll
    for (int o = 16; o; o >>= 1) s += __shfl_xor_sync(0xffffffffu, s, o);
    if (!lane) ss[wid] = s;
    __syncthreads();
    s = ss[0] + ss[1] + ss[2] + ss[3] + ss[4] + ss[5] + ss[6] + ss[7];

    const float inv = 1.0f / s;
    #pragma unroll
    for (int i = 0; i < 8; i++) row[i * 256 + tid] = v[i] * inv;
}

// ---------------- (residual +) LayerNorm over D=512 ----------------
template<bool ADD>
__global__ __launch_bounds__(128)
void ln_kernel(const float* __restrict__ X, const float* __restrict__ R,
               const float* __restrict__ gw, const float* __restrict__ bw,
               float* __restrict__ out)
{
    const int tid = threadIdx.x;
    const size_t base = (size_t)blockIdx.x * PD;

    float4 xv = ((const float4*)(X + base))[tid];
    if (ADD) {
        float4 av = ((const float4*)(R + base))[tid];
        xv.x += av.x; xv.y += av.y; xv.z += av.z; xv.w += av.w;
    }
    float s = xv.x + xv.y + xv.z + xv.w;
    float q = xv.x * xv.x + xv.y * xv.y + xv.z * xv.z + xv.w * xv.w;
    #pragma unroll
    for (int o = 16; o; o >>= 1) {
        s += __shfl_xor_sync(0xffffffffu, s, o);
        q += __shfl_xor_sync(0xffffffffu, q, o);
    }
    __shared__ float rs[4], rq[4];
    const int lane = tid & 31, wid = tid >> 5;
    if (!lane) { rs[wid] = s; rq[wid] = q; }
    __syncthreads();
    s = rs[0] + rs[1] + rs[2] + rs[3];
    q = rq[0] + rq[1] + rq[2] + rq[3];

    const float mean = s * (1.0f / 512.0f);
    const float var  = q * (1.0f / 512.0f) - mean * mean;
    const float rstd = rsqrtf(var + 1e-5f);

    float4 gv = ((const float4*)gw)[tid];
    float4 bv = ((const float4*)bw)[tid];
    float4 o;
    o.x = (xv.x - mean) * rstd * gv.x + bv.x;
    o.y = (xv.y - mean) * rstd * gv.y + bv.y;
    o.z = (xv.z - mean) * rstd * gv.z + bv.z;
    o.w = (xv.w - mean) * rstd * gv.w + bv.w;
    ((float4*)(out + base))[tid] = o;
}

// ---------------- launch ----------------
extern "C" void kernel_launch(void* const* d_in, const int* in_sizes, int n_in,
                              void* d_out, int out_size)
{
    (void)in_sizes; (void)n_in; (void)out_size;

    const float* x    = (const float*)d_in[0];
    const float* Wq   = (const float*)d_in[1];
    const float* bq   = (const float*)d_in[2];
    const float* Wk   = (const float*)d_in[3];
    const float* bk   = (const float*)d_in[4];
    const float* Wv   = (const float*)d_in[5];
    const float* bv   = (const float*)d_in[6];
    const float* ln0g = (const float*)d_in[7];
    const float* ln0b = (const float*)d_in[8];
    const float* W1   = (const float*)d_in[9];
    const float* b1   = (const float*)d_in[10];
    const float* ln1g = (const float*)d_in[11];
    const float* ln1b = (const float*)d_in[12];
    const float* W2   = (const float*)d_in[13];
    const float* b2   = (const float*)d_in[14];
    const float* ln2g = (const float*)d_in[15];
    const float* ln2b = (const float*)d_in[16];
    const float* W3   = (const float*)d_in[17];
    const float* b3   = (const float*)d_in[18];
    float* out = (float*)d_out;

    float *q, *k, *v, *att, *onxt, *sc;
    cudaGetSymbolAddress((void**)&q,    g_q);
    cudaGetSymbolAddress((void**)&k,    g_k);
    cudaGetSymbolAddress((void**)&v,    g_v);
    cudaGetSymbolAddress((void**)&att,  g_att);
    cudaGetSymbolAddress((void**)&onxt, g_onxt);
    cudaGetSymbolAddress((void**)&sc,   g_sc);

    // recycle score buffer for FFN intermediates (attention done by then)
    const size_t SEG = (size_t)PM * PD;   // 8,388,608 floats; 4*SEG == |g_sc|
    float* t1 = sc;
    float* h1 = sc + SEG;
    float* t2 = sc + 2 * SEG;
    float* h2 = sc + 3 * SEG;

    const dim3 blk(256);
    const dim3 gQKV(PD / BN, PM / BM, 1);          // (4,128)
    const dim3 gSC (PS / BN, PS / BM, PB);         // (16,16,8)
    const dim3 gATT(PD / BN, PS / BM, PB);         // (4,16,8)
    const long long sQK = (long long)PS * PD;      // per-batch q/k/v stride
    const long long sSS = (long long)PS * PS;      // per-batch score stride

    // 1-3: QKV projections
    gemm_kernel<0,false><<<gQKV, blk>>>(x, Wq, bq, nullptr, q, PM, PD, PD, 0, 0, 0, 1.0f);
    gemm_kernel<0,false><<<gQKV, blk>>>(x, Wk, bk, nullptr, k, PM, PD, PD, 0, 0, 0, 1.0f);
    gemm_kernel<0,false><<<gQKV, blk>>>(x, Wv, bv, nullptr, v, PM, PD, PD, 0, 0, 0, 1.0f);

    // 4: scores = scale * q @ k^T   (batched NT)
    gemm_kernel<1,true><<<gSC, blk>>>(q, k, nullptr, nullptr, sc,
                                      PS, PS, PD, sQK, sQK, sSS, SQD);
    // 5: row softmax
    softmax_kernel<<<PB * PS, 256>>>(sc);

    // 6: att = w @ v   (batched NN)
    gemm_kernel<0,false><<<gATT, blk>>>(sc, v, nullptr, nullptr, att,
                                        PS, PD, PS, sSS, sQK, sQK, 1.0f);

    // 7: out_nxt = LN(x + att)
    ln_kernel<true><<<PM, 128>>>(x, att, ln0g, ln0b, onxt);

    // 8-9: h1 = LN(gelu(onxt + onxt@W1 + b1))
    gemm_kernel<2,false><<<gQKV, blk>>>(onxt, W1, b1, onxt, t1, PM, PD, PD, 0, 0, 0, 1.0f);
    ln_kernel<false><<<PM, 128>>>(t1, nullptr, ln1g, ln1b, h1);

    // 10-11: h2 = LN(gelu(onxt + h1@W2 + b2))
    gemm_kernel<2,false><<<gQKV, blk>>>(h1, W2, b2, onxt, t2, PM, PD, PD, 0, 0, 0, 1.0f);
    ln_kernel<false><<<PM, 128>>>(t2, nullptr, ln2g, ln2b, h2);

    // 12: out = h2 @ W3 + b3
    gemm_kernel<0,false><<<gQKV, blk>>>(h2, W3, b3, nullptr, out, PM, PD, PD, 0, 0, 0, 1.0f);
}

// round 10
// speedup vs baseline: 2.0782x; 2.0782x over previous
#include <cuda_runtime.h>
#include <cuda_bf16.h>
#include <math.h>

// Problem constants
#define PB   8
#define PS   2048
#define PD   512
#define PM   (PB * PS)               // 16384 rows flattened
#define SQD  0.044194173824159216f   // 1/sqrt(512)

// ---------------- scratch (no allocations allowed) ----------------
__device__ float g_q    [PB * PS * PD];
__device__ float g_k    [PB * PS * PD];
__device__ float g_v    [PB * PS * PD];
__device__ float g_att  [PB * PS * PD];
__device__ float g_onxt [PB * PS * PD];
__device__ float g_sc   [PB * PS * PS];   // 134 MB; recycled for t1/h1/t2/h2

__device__ __forceinline__ float gelu_exact(float x) {
    return 0.5f * x * (1.0f + erff(x * 0.70710678118654752f));
}

// ================= bf16 split GEMM on tensor cores ==================
// C[M,N] = A[M,K] @ B + epilogue, fp32 in/out.
// Each fp32 split into bf16 hi + lo; D = Ah*Bh + Ah*Bl + Al*Bh (fp32 accum).
// BT=false: B is [K,N] row-major (NN).  BT=true: B is [N,K] row-major (NT).
// EPI 0: C = acc (+ bias[n])         EPI 1: C = acc * scale
// EPI 2: C = gelu(acc + bias[n] + res[m,n])
#define BM 128
#define BN 128
#define BK 32
#define LDS 40   // padded row length (bf16 elems): 80B stride, ldmatrix conflict-free

__device__ __forceinline__ void ldsm4(unsigned &r0, unsigned &r1, unsigned &r2, unsigned &r3, unsigned addr) {
    asm volatile("ldmatrix.sync.aligned.m8n8.x4.shared.b16 {%0,%1,%2,%3}, [%4];\n"
                 : "=r"(r0), "=r"(r1), "=r"(r2), "=r"(r3) : "r"(addr));
}
__device__ __forceinline__ void ldsm2(unsigned &r0, unsigned &r1, unsigned addr) {
    asm volatile("ldmatrix.sync.aligned.m8n8.x2.shared.b16 {%0,%1}, [%2];\n"
                 : "=r"(r0), "=r"(r1) : "r"(addr));
}
__device__ __forceinline__ void mma16816(float c[4], unsigned a0, unsigned a1, unsigned a2, unsigned a3,
                                         unsigned b0, unsigned b1) {
    asm volatile("mma.sync.aligned.m16n8k16.row.col.f32.bf16.bf16.f32 "
                 "{%0,%1,%2,%3},{%4,%5,%6,%7},{%8,%9},{%0,%1,%2,%3};\n"
                 : "+f"(c[0]), "+f"(c[1]), "+f"(c[2]), "+f"(c[3])
                 : "r"(a0), "r"(a1), "r"(a2), "r"(a3), "r"(b0), "r"(b1));
}

// split a float4 into 4 (hi,lo) bf16 pairs and store 8B each
__device__ __forceinline__ void store_split4(__nv_bfloat16* hp, __nv_bfloat16* lp, float4 v) {
    __align__(8) __nv_bfloat16 h[4], l[4];
    float e0 = v.x, e1 = v.y, e2 = v.z, e3 = v.w;
    h[0] = __float2bfloat16(e0); l[0] = __float2bfloat16(e0 - __bfloat162float(h[0]));
    h[1] = __float2bfloat16(e1); l[1] = __float2bfloat16(e1 - __bfloat162float(h[1]));
    h[2] = __float2bfloat16(e2); l[2] = __float2bfloat16(e2 - __bfloat162float(h[2]));
    h[3] = __float2bfloat16(e3); l[3] = __float2bfloat16(e3 - __bfloat162float(h[3]));
    *(uint2*)hp = *(uint2*)h;
    *(uint2*)lp = *(uint2*)l;
}

template<int EPI, bool BT>
__global__ __launch_bounds__(256, 2)
void gemm_kernel(const float* __restrict__ A, const float* __restrict__ B,
                 const float* __restrict__ bias, const float* __restrict__ res,
                 float* __restrict__ C, int M, int N, int K,
                 long long sA, long long sB, long long sC, float scale)
{
    __shared__ __nv_bfloat16 Ah[BM][LDS], Al[BM][LDS];
    __shared__ __nv_bfloat16 Bh[BN][LDS], Bl[BN][LDS];

    const int tid  = threadIdx.x;
    const int lane = tid & 31;
    const int warp = tid >> 5;
    const int wm   = warp >> 2;     // 0..1
    const int wn   = warp & 3;      // 0..3
    const int m0   = blockIdx.y * BM;
    const int n0   = blockIdx.x * BN;

    A += (long long)blockIdx.z * sA;
    B += (long long)blockIdx.z * sB;
    C += (long long)blockIdx.z * sC;

    const int lda = K;
    const int ldb = BT ? K : N;

    // global-load coordinates
    const int r2 = tid >> 1;              // 0..127: row for A (and NT-B)
    const int kq = (tid & 1) * 16;        // k base, 4 float4s at kq+4i
    const int kr = tid >> 3;              // 0..31 : k row for NN-B
    const int nc = (tid & 7) * 4;         // n base for NN-B, +32*i

    // ldmatrix per-thread base addresses (loop-invariant)
    const int la15 = lane & 15;
    const int arow = wm * 64 + la15;
    const int acol = (lane >> 4) * 8;
    const int brow = wn * 32 + (la15 & 7);
    const int bcol = ((la15 >> 3) & 1) * 8;
    const unsigned aHiB = (unsigned)__cvta_generic_to_shared(&Ah[arow][acol]);
    const unsigned aLoB = (unsigned)__cvta_generic_to_shared(&Al[arow][acol]);
    const unsigned bHiB = (unsigned)__cvta_generic_to_shared(&Bh[brow][bcol]);
    const unsigned bLoB = (unsigned)__cvta_generic_to_shared(&Bl[brow][bcol]);

    float c[4][4][4];
    #pragma unroll
    for (int i = 0; i < 4; i++)
        #pragma unroll
        for (int j = 0; j < 4; j++)
            #pragma unroll
            for (int e = 0; e < 4; e++) c[i][j][e] = 0.0f;

    for (int k0 = 0; k0 < K; k0 += BK) {
        // ---- A tile [BM x BK] -> Ah/Al[r][k] ----
        {
            const float* Ap = A + (size_t)(m0 + r2) * lda + k0 + kq;
            #pragma unroll
            for (int i = 0; i < 4; i++) {
                float4 v = *(const float4*)(Ap + 4 * i);
                store_split4(&Ah[r2][kq + 4 * i], &Al[r2][kq + 4 * i], v);
            }
        }
        // ---- B tile -> Bh/Bl[n][k] ----
        if (BT) {  // B[N,K]: direct rows
            const float* Bp = B + (size_t)(n0 + r2) * ldb + k0 + kq;
            #pragma unroll
            for (int i = 0; i < 4; i++) {
                float4 v = *(const float4*)(Bp + 4 * i);
                store_split4(&Bh[r2][kq + 4 * i], &Bl[r2][kq + 4 * i], v);
            }
        } else {   // B[K,N]: transpose while storing
            const float* Bp = B + (size_t)(k0 + kr) * ldb + n0;
            #pragma unroll
            for (int i = 0; i < 4; i++) {
                int n = nc + i * 32;
                float4 v = *(const float4*)(Bp + n);
                float e[4] = {v.x, v.y, v.z, v.w};
                #pragma unroll
                for (int j = 0; j < 4; j++) {
                    __nv_bfloat16 h = __float2bfloat16(e[j]);
                    __nv_bfloat16 l = __float2bfloat16(e[j] - __bfloat162float(h));
                    Bh[n + j][kr] = h;
                    Bl[n + j][kr] = l;
                }
            }
        }
        __syncthreads();

        #pragma unroll
        for (int ks = 0; ks < BK; ks += 16) {
            unsigned ah[4][4], al[4][4], bh[4][2], bl[4][2];
            // hi fragments
            #pragma unroll
            for (int mt = 0; mt < 4; mt++)
                ldsm4(ah[mt][0], ah[mt][1], ah[mt][2], ah[mt][3],
                      aHiB + (unsigned)((mt * 16 * LDS + ks) * 2));
            #pragma unroll
            for (int nt = 0; nt < 4; nt++)
                ldsm2(bh[nt][0], bh[nt][1],
                      bHiB + (unsigned)((nt * 8 * LDS + ks) * 2));
            // hi*hi
            #pragma unroll
            for (int mt = 0; mt < 4; mt++)
                #pragma unroll
                for (int nt = 0; nt < 4; nt++)
                    mma16816(c[mt][nt], ah[mt][0], ah[mt][1], ah[mt][2], ah[mt][3],
                             bh[nt][0], bh[nt][1]);
            // lo*hi
            #pragma unroll
            for (int mt = 0; mt < 4; mt++)
                ldsm4(al[mt][0], al[mt][1], al[mt][2], al[mt][3],
                      aLoB + (unsigned)((mt * 16 * LDS + ks) * 2));
            #pragma unroll
            for (int mt = 0; mt < 4; mt++)
                #pragma unroll
                for (int nt = 0; nt < 4; nt++)
                    mma16816(c[mt][nt], al[mt][0], al[mt][1], al[mt][2], al[mt][3],
                             bh[nt][0], bh[nt][1]);
            // hi*lo
            #pragma unroll
            for (int nt = 0; nt < 4; nt++)
                ldsm2(bl[nt][0], bl[nt][1],
                      bLoB + (unsigned)((nt * 8 * LDS + ks) * 2));
            #pragma unroll
            for (int mt = 0; mt < 4; mt++)
                #pragma unroll
                for (int nt = 0; nt < 4; nt++)
                    mma16816(c[mt][nt], ah[mt][0], ah[mt][1], ah[mt][2], ah[mt][3],
                             bl[nt][0], bl[nt][1]);
        }
        __syncthreads();
    }

    // ---- epilogue ----
    const int er = lane >> 2;         // 0..7
    const int ec = (lane & 3) * 2;    // even col
    const int m_base = m0 + wm * 64;
    const int n_base = n0 + wn * 32;

    #pragma unroll
    for (int mt = 0; mt < 4; mt++) {
        #pragma unroll
        for (int nt = 0; nt < 4; nt++) {
            const int n = n_base + nt * 8 + ec;
            #pragma unroll
            for (int half = 0; half < 2; half++) {
                const size_t m = (size_t)(m_base + mt * 16 + er + half * 8);
                float2 o;
                o.x = c[mt][nt][half * 2 + 0];
                o.y = c[mt][nt][half * 2 + 1];
                if (EPI == 1) {
                    o.x *= scale; o.y *= scale;
                } else if (EPI == 0) {
                    if (bias) {
                        float2 bb = *(const float2*)&bias[n];
                        o.x += bb.x; o.y += bb.y;
                    }
                } else if (EPI == 2) {
                    float2 bb = *(const float2*)&bias[n];
                    float2 rr = *(const float2*)&res[m * (size_t)N + n];
                    o.x = gelu_exact(o.x + bb.x + rr.x);
                    o.y = gelu_exact(o.y + bb.y + rr.y);
                }
                *(float2*)&C[m * (size_t)N + n] = o;
            }
        }
    }
}

// ---------------- row softmax over 2048 cols ----------------
__global__ __launch_bounds__(256)
void softmax_kernel(float* __restrict__ Sc)
{
    float* row = Sc + (size_t)blockIdx.x * PS;
    const int tid  = threadIdx.x;
    const int lane = tid & 31;
    const int wid  = tid >> 5;

    float v[8];
    float mx = -3.4e38f;
    #pragma unroll
    for (int i = 0; i < 8; i++) { v[i] = row[i * 256 + tid]; mx = fmaxf(mx, v[i]); }
    #pragma unroll
    for (int o = 16; o; o >>= 1) mx = fmaxf(mx, __shfl_xor_sync(0xffffffffu, mx, o));

    __shared__ float sm[8], ss[8];
    if (!lane) sm[wid] = mx;
    __syncthreads();
    mx = sm[0];
    #pragma unroll
    for (int i = 1; i < 8; i++) mx = fmaxf(mx, sm[i]);

    float s = 0.0f;
    #pragma unroll
    for (int i = 0; i < 8; i++) { v[i] = expf(v[i] - mx); s += v[i]; }
    #pragma unroll
    for (int o = 16; o; o >>= 1) s += __shfl_xor_sync(0xffffffffu, s, o);
    if (!lane) ss[wid] = s;
    __syncthreads();
    s = ss[0] + ss[1] + ss[2] + ss[3] + ss[4] + ss[5] + ss[6] + ss[7];

    const float inv = 1.0f / s;
    #pragma unroll
    for (int i = 0; i < 8; i++) row[i * 256 + tid] = v[i] * inv;
}

// ---------------- (residual +) LayerNorm over D=512 ----------------
template<bool ADD>
__global__ __launch_bounds__(128)
void ln_kernel(const float* __restrict__ X, const float* __restrict__ R,
               const float* __restrict__ gw, const float* __restrict__ bw,
               float* __restrict__ out)
{
    const int tid = threadIdx.x;
    const size_t base = (size_t)blockIdx.x * PD;

    float4 xv = ((const float4*)(X + base))[tid];
    if (ADD) {
        float4 av = ((const float4*)(R + base))[tid];
        xv.x += av.x; xv.y += av.y; xv.z += av.z; xv.w += av.w;
    }
    float s = xv.x + xv.y + xv.z + xv.w;
    float q = xv.x * xv.x + xv.y * xv.y + xv.z * xv.z + xv.w * xv.w;
    #pragma unroll
    for (int o = 16; o; o >>= 1) {
        s += __shfl_xor_sync(0xffffffffu, s, o);
        q += __shfl_xor_sync(0xffffffffu, q, o);
    }
    __shared__ float rs[4], rq[4];
    const int lane = tid & 31, wid = tid >> 5;
    if (!lane) { rs[wid] = s; rq[wid] = q; }
    __syncthreads();
    s = rs[0] + rs[1] + rs[2] + rs[3];
    q = rq[0] + rq[1] + rq[2] + rq[3];

    const float mean = s * (1.0f / 512.0f);
    const float var  = q * (1.0f / 512.0f) - mean * mean;
    const float rstd = rsqrtf(var + 1e-5f);

    float4 gv = ((const float4*)gw)[tid];
    float4 bv = ((const float4*)bw)[tid];
    float4 o;
    o.x = (xv.x - mean) * rstd * gv.x + bv.x;
    o.y = (xv.y - mean) * rstd * gv.y + bv.y;
    o.z = (xv.z - mean) * rstd * gv.z + bv.z;
    o.w = (xv.w - mean) * rstd * gv.w + bv.w;
    ((float4*)(out + base))[tid] = o;
}

// ---------------- launch ----------------
extern "C" void kernel_launch(void* const* d_in, const int* in_sizes, int n_in,
                              void* d_out, int out_size)
{
    (void)in_sizes; (void)n_in; (void)out_size;

    const float* x    = (const float*)d_in[0];
    const float* Wq   = (const float*)d_in[1];
    const float* bq   = (const float*)d_in[2];
    const float* Wk   = (const float*)d_in[3];
    const float* bk   = (const float*)d_in[4];
    const float* Wv   = (const float*)d_in[5];
    const float* bv   = (const float*)d_in[6];
    const float* ln0g = (const float*)d_in[7];
    const float* ln0b = (const float*)d_in[8];
    const float* W1   = (const float*)d_in[9];
    const float* b1   = (const float*)d_in[10];
    const float* ln1g = (const float*)d_in[11];
    const float* ln1b = (const float*)d_in[12];
    const float* W2   = (const float*)d_in[13];
    const float* b2   = (const float*)d_in[14];
    const float* ln2g = (const float*)d_in[15];
    const float* ln2b = (const float*)d_in[16];
    const float* W3   = (const float*)d_in[17];
    const float* b3   = (const float*)d_in[18];
    float* out = (float*)d_out;

    float *q, *k, *v, *att, *onxt, *sc;
    cudaGetSymbolAddress((void**)&q,    g_q);
    cudaGetSymbolAddress((void**)&k,    g_k);
    cudaGetSymbolAddress((void**)&v,    g_v);
    cudaGetSymbolAddress((void**)&att,  g_att);
    cudaGetSymbolAddress((void**)&onxt, g_onxt);
    cudaGetSymbolAddress((void**)&sc,   g_sc);

    // recycle score buffer for FFN intermediates (attention done by then)
    const size_t SEG = (size_t)PM * PD;
    float* t1 = sc;
    float* h1 = sc + SEG;
    float* t2 = sc + 2 * SEG;
    float* h2 = sc + 3 * SEG;

    const dim3 blk(256);
    const dim3 gQKV(PD / BN, PM / BM, 1);          // (4,128)
    const dim3 gSC (PS / BN, PS / BM, PB);         // (16,16,8)
    const dim3 gATT(PD / BN, PS / BM, PB);         // (4,16,8)
    const long long sQK = (long long)PS * PD;
    const long long sSS = (long long)PS * PS;

    // 1-3: QKV projections
    gemm_kernel<0,false><<<gQKV, blk>>>(x, Wq, bq, nullptr, q, PM, PD, PD, 0, 0, 0, 1.0f);
    gemm_kernel<0,false><<<gQKV, blk>>>(x, Wk, bk, nullptr, k, PM, PD, PD, 0, 0, 0, 1.0f);
    gemm_kernel<0,false><<<gQKV, blk>>>(x, Wv, bv, nullptr, v, PM, PD, PD, 0, 0, 0, 1.0f);

    // 4: scores = scale * q @ k^T   (batched NT)
    gemm_kernel<1,true><<<gSC, blk>>>(q, k, nullptr, nullptr, sc,
                                      PS, PS, PD, sQK, sQK, sSS, SQD);
    // 5: row softmax
    softmax_kernel<<<PB * PS, 256>>>(sc);

    // 6: att = w @ v   (batched NN)
    gemm_kernel<0,false><<<gATT, blk>>>(sc, v, nullptr, nullptr, att,
                                        PS, PD, PS, sSS, sQK, sQK, 1.0f);

    // 7: out_nxt = LN(x + att)
    ln_kernel<true><<<PM, 128>>>(x, att, ln0g, ln0b, onxt);

    // 8-9: h1 = LN(gelu(onxt + onxt@W1 + b1))
    gemm_kernel<2,false><<<gQKV, blk>>>(onxt, W1, b1, onxt, t1, PM, PD, PD, 0, 0, 0, 1.0f);
    ln_kernel<false><<<PM, 128>>>(t1, nullptr, ln1g, ln1b, h1);

    // 10-11: h2 = LN(gelu(onxt + h1@W2 + b2))
    gemm_kernel<2,false><<<gQKV, blk>>>(h1, W2, b2, onxt, t2, PM, PD, PD, 0, 0, 0, 1.0f);
    ln_kernel<false><<<PM, 128>>>(t2, nullptr, ln2g, ln2b, h2);

    // 12: out = h2 @ W3 + b3
    gemm_kernel<0,false><<<gQKV, blk>>>(h2, W3, b3, nullptr, out, PM, PD, PD, 0, 0, 0, 1.0f);
}